// round 10
// baseline (speedup 1.0000x reference)
#include <cuda_runtime.h>
#include <cuda_bf16.h>
#include <math.h>
#include <stdint.h>

// ---------------- problem constants ----------------
#define TOK    8192
#define DMODEL 1024
#define NH     16
#define DH     64
#define MSEQ   2048
#define NB     4
#define QKVS   3072

typedef __nv_bfloat16 bf16;

// ---------------- scratch ----------------------------------------------------
__device__ float g_x1 [TOK * DMODEL];
__device__ float g_bqkv[3072];

__device__ bf16 g_xnb [TOK * DMODEL];
__device__ bf16 g_Pb  [TOK * 768];
__device__ bf16 g_QKV [TOK * QKVS];
__device__ bf16 g_AOb [TOK * DMODEL];
__device__ bf16 g_Gb  [TOK * 2048];
__device__ bf16 g_Tb  [TOK * 512];

// bf16 weights, [N,K] K-major
__device__ bf16 w_Uqkv[768 * 1024];
__device__ bf16 w_Vqkv[3072 * 256];
__device__ bf16 w_Wo[1024 * 1024];
__device__ bf16 w_U1[512 * 1024];
__device__ bf16 w_V1[4096 * 512];       // geglu-interleaved rows
__device__ bf16 w_U2[512 * 2048];
__device__ bf16 w_V2[1024 * 512];

// ---------------- asm helpers ------------------------------------------------
__device__ __forceinline__ uint32_t s2u(const void* p) {
    uint32_t a;
    asm("{ .reg .u64 t; cvta.to.shared.u64 t, %1; cvt.u32.u64 %0, t; }" : "=r"(a) : "l"(p));
    return a;
}
__device__ __forceinline__ void cp16(uint32_t saddr, const void* gptr) {
    asm volatile("cp.async.cg.shared.global [%0], [%1], 16;" :: "r"(saddr), "l"(gptr));
}
#define CP_COMMIT() asm volatile("cp.async.commit_group;" ::: "memory")
#define CP_WAIT(n)  asm volatile("cp.async.wait_group %0;" :: "n"(n) : "memory")

__device__ __forceinline__ void ldsm4(uint32_t& r0, uint32_t& r1, uint32_t& r2,
                                      uint32_t& r3, uint32_t addr) {
    asm volatile("ldmatrix.sync.aligned.m8n8.x4.shared.b16 {%0,%1,%2,%3}, [%4];"
                 : "=r"(r0), "=r"(r1), "=r"(r2), "=r"(r3) : "r"(addr));
}
__device__ __forceinline__ void ldsm4t(uint32_t& r0, uint32_t& r1, uint32_t& r2,
                                       uint32_t& r3, uint32_t addr) {
    asm volatile("ldmatrix.sync.aligned.m8n8.x4.trans.shared.b16 {%0,%1,%2,%3}, [%4];"
                 : "=r"(r0), "=r"(r1), "=r"(r2), "=r"(r3) : "r"(addr));
}
__device__ __forceinline__ void mma16816(float* d, const uint32_t* a, const uint32_t* b) {
    asm volatile(
        "mma.sync.aligned.m16n8k16.row.col.f32.bf16.bf16.f32 "
        "{%0,%1,%2,%3}, {%4,%5,%6,%7}, {%8,%9}, {%0,%1,%2,%3};"
        : "+f"(d[0]), "+f"(d[1]), "+f"(d[2]), "+f"(d[3])
        : "r"(a[0]), "r"(a[1]), "r"(a[2]), "r"(a[3]), "r"(b[0]), "r"(b[1]));
}
__device__ __forceinline__ uint32_t packbf(float lo, float hi) {
    uint32_t d;
    asm("cvt.rn.bf16x2.f32 %0, %1, %2;" : "=r"(d) : "f"(hi), "f"(lo));
    return d;
}
__device__ __forceinline__ float ex2(float x) {
    float r;
    asm("ex2.approx.f32 %0, %1;" : "=f"(r) : "f"(x));
    return r;
}
__device__ __forceinline__ float gelu_t(float a) {
    float inner = 0.7978845608028654f * (a + 0.044715f * a * a * a);
    return 0.5f * a * (1.0f + tanhf(inner));
}
// full 8-way swizzle for 128B rows (BK=64 bf16)
#define SWZ64(r, cc) ((uint32_t)((r) * 128 + (((cc) ^ ((r) & 7)) << 4)))

// ---------------- HMMA GEMM: C[M,Jout] = A[M,K](lda) * B[J,K]^T --------------
// 128x256 block, 8 warps of 64x64, BK=64, 3-stage cp.async, 1 CTA/SM.
#define GSTG 49152                       // per-stage: A 16KB + B 32KB
#define GEMM_SMEM (3 * GSTG)
template<bool HASBIAS, bool HASRES, bool OUTBF16, bool GEGLU, bool QKV>
__global__ void __launch_bounds__(256, 1)
mma_gemm(const bf16* __restrict__ A, const bf16* __restrict__ B,
         const float* __restrict__ bias, const float* __restrict__ res,
         float* __restrict__ Cf, bf16* __restrict__ Cb, int K, int lda, int J) {
    extern __shared__ char gsm[];
    const int tid = threadIdx.x;
    const int wid = tid >> 5, lane = tid & 31;
    const int g = lane >> 3;
    const int bm = blockIdx.y * 128, bn = blockIdx.x * 256;
    const int wm = wid >> 2;             // 0..1  (64 rows)
    const int wn = wid & 3;              // 0..3  (64 cols)
    uint32_t sAb[3], sBb[3];
#pragma unroll
    for (int i = 0; i < 3; i++) {
        sAb[i] = s2u(gsm) + i * GSTG;
        sBb[i] = s2u(gsm) + i * GSTG + 16384;
    }

    const bf16* Ag = A + (size_t)bm * lda + (QKV ? (bn >> 10) * 256 : 0);
    const bf16* Bg = B + (size_t)bn * K;

    auto load = [&](int c, int buf) {
        int k0 = c * 64;
#pragma unroll
        for (int i = 0; i < 4; i++) {            // A: 128 rows
            int v = tid + i * 256;
            int r = v >> 3, cc = v & 7;
            cp16(sAb[buf] + SWZ64(r, cc), Ag + (size_t)r * lda + k0 + cc * 8);
        }
#pragma unroll
        for (int i = 0; i < 8; i++) {            // B: 256 rows
            int v = tid + i * 256;
            int r = v >> 3, cc = v & 7;
            cp16(sBb[buf] + SWZ64(r, cc), Bg + (size_t)r * K + k0 + cc * 8);
        }
        CP_COMMIT();
    };

    float acc[4][8][4];
#pragma unroll
    for (int mi = 0; mi < 4; mi++)
#pragma unroll
        for (int ni = 0; ni < 8; ni++)
#pragma unroll
            for (int q = 0; q < 4; q++) acc[mi][ni][q] = 0.f;

    const int NC = K / 64;
    load(0, 0);
    if (NC > 1) load(1, 1);

    int bcur = 0, bpre = 2;
    for (int c = 0; c < NC; c++) {
        if (c + 1 < NC) { CP_WAIT(1); } else { CP_WAIT(0); }
        __syncthreads();
        if (c + 2 < NC) load(c + 2, bpre);
        const int buf = bcur;
#pragma unroll
        for (int ks = 0; ks < 4; ks++) {
            uint32_t a[4][4], b[8][2];
#pragma unroll
            for (int mi = 0; mi < 4; mi++) {
                int r = wm * 64 + mi * 16 + (lane & 7) + ((g & 1) << 3);
                int cc = ks * 2 + (g >> 1);
                ldsm4(a[mi][0], a[mi][1], a[mi][2], a[mi][3], sAb[buf] + SWZ64(r, cc));
            }
#pragma unroll
            for (int pi = 0; pi < 4; pi++) {
                int r = wn * 64 + pi * 16 + (lane & 7) + ((g >> 1) << 3);
                int cc = ks * 2 + (g & 1);
                ldsm4(b[pi * 2][0], b[pi * 2][1], b[pi * 2 + 1][0], b[pi * 2 + 1][1],
                      sBb[buf] + SWZ64(r, cc));
            }
#pragma unroll
            for (int mi = 0; mi < 4; mi++)
#pragma unroll
                for (int ni = 0; ni < 8; ni++)
                    mma16816(acc[mi][ni], a[mi], b[ni]);
        }
        bcur = (bcur == 2) ? 0 : bcur + 1;
        bpre = (bpre == 2) ? 0 : bpre + 1;
    }

    if (GEGLU) {
        // packed cols: even 8-groups = h1, odd = h2; dest col base = packed/2
#pragma unroll
        for (int mi = 0; mi < 4; mi++) {
#pragma unroll
            for (int half = 0; half < 2; half++) {
                int row = bm + wm * 64 + mi * 16 + (lane >> 2) + half * 8;
#pragma unroll
                for (int ni = 0; ni < 8; ni += 2) {
                    int pcb = bn + wn * 64 + ni * 8;
                    int dc = pcb / 2 + (lane & 3) * 2;
                    float h1a = acc[mi][ni][half * 2 + 0];
                    float h1b = acc[mi][ni][half * 2 + 1];
                    float h2a = acc[mi][ni + 1][half * 2 + 0];
                    float h2b = acc[mi][ni + 1][half * 2 + 1];
                    if (HASBIAS) {
                        h1a += bias[dc];        h1b += bias[dc + 1];
                        h2a += bias[2048 + dc]; h2b += bias[2048 + dc + 1];
                    }
                    float g0 = gelu_t(h1a) * h2a;
                    float g1 = gelu_t(h1b) * h2b;
                    *(uint32_t*)&Cb[(size_t)row * 2048 + dc] = packbf(g0, g1);
                }
            }
        }
        return;
    }

#pragma unroll
    for (int mi = 0; mi < 4; mi++) {
#pragma unroll
        for (int half = 0; half < 2; half++) {
            int row = bm + wm * 64 + mi * 16 + (lane >> 2) + half * 8;
#pragma unroll
            for (int ni = 0; ni < 8; ni++) {
                int col = bn + wn * 64 + ni * 8 + (lane & 3) * 2;
                float v0 = acc[mi][ni][half * 2 + 0];
                float v1 = acc[mi][ni][half * 2 + 1];
                if (HASBIAS) { v0 += bias[col]; v1 += bias[col + 1]; }
                if (HASRES) {
                    const float2 rv = *(const float2*)&res[(size_t)row * J + col];
                    v0 += rv.x; v1 += rv.y;
                }
                if (OUTBF16) {
                    *(uint32_t*)&Cb[(size_t)row * J + col] = packbf(v0, v1);
                } else {
                    *(float2*)&Cf[(size_t)row * J + col] = make_float2(v0, v1);
                }
            }
        }
    }
}

// ---------------- merged weight prep ------------------------------------------
__global__ void __launch_bounds__(256)
prep_kernel(const float* __restrict__ Uq, const float* __restrict__ Uk,
            const float* __restrict__ Uv, const float* __restrict__ Vq,
            const float* __restrict__ Vk, const float* __restrict__ Vv,
            const float* __restrict__ Wo, const float* __restrict__ U1,
            const float* __restrict__ V1, const float* __restrict__ U2,
            const float* __restrict__ V2,
            const float* __restrict__ bq, const float* __restrict__ bk,
            const float* __restrict__ bv,
            bf16* __restrict__ wUqkv, bf16* __restrict__ wVqkv,
            bf16* __restrict__ wWo, bf16* __restrict__ wU1,
            bf16* __restrict__ wV1, bf16* __restrict__ wU2, bf16* __restrict__ wV2,
            float* __restrict__ bqkv) {
    __shared__ float t[32][33];
    int bid = blockIdx.x;
    const int tx32 = threadIdx.x & 31, ty8 = threadIdx.x >> 5;
    const float* in; bf16* out;
    int K, N, mode = 0;
    if (bid < 768) {
        int j = bid / 256; bid &= 255;
        in = (j == 0) ? Uq : (j == 1) ? Uk : Uv;
        out = wUqkv + j * 256 * 1024; K = 1024; N = 256;
    } else if (bid < 1536) {
        int j = (bid - 768) / 256; bid = (bid - 768) & 255;
        in = (j == 0) ? Vq : (j == 1) ? Vk : Vv;
        out = wVqkv + j * 1024 * 256; K = 256; N = 1024;
    } else if (bid < 2048) { in = U1; out = wU1; K = 1024; N = 512;  bid -= 1536; }
    else if (bid < 2560)   { in = V2; out = wV2; K = 512;  N = 1024; bid -= 2048; }
    else if (bid < 3584)   { in = U2; out = wU2; K = 2048; N = 512;  bid -= 2560; }
    else if (bid < 5632)   { in = V1; out = wV1; K = 512;  N = 4096; bid -= 3584; mode = 1; }
    else if (bid < 6656) {
        size_t base = (size_t)(bid - 5632) * 1024 + threadIdx.x * 4;
        float4 v = *(const float4*)(Wo + base);
        bf16 h[4];
        h[0] = __float2bfloat16_rn(v.x); h[1] = __float2bfloat16_rn(v.y);
        h[2] = __float2bfloat16_rn(v.z); h[3] = __float2bfloat16_rn(v.w);
        *(uint2*)(wWo + base) = *(uint2*)h;
        return;
    } else {
        for (int i = threadIdx.x; i < 1024; i += 256) {
            bqkv[i]        = bq[i];
            bqkv[1024 + i] = bk[i];
            bqkv[2048 + i] = bv[i];
        }
        return;
    }
    const int nt = N / 32;
    int k0 = (bid / nt) * 32, n0 = (bid % nt) * 32;
    for (int i = ty8; i < 32; i += 8)
        t[i][tx32] = in[(size_t)(k0 + i) * N + n0 + tx32];
    __syncthreads();
    for (int i = ty8; i < 32; i += 8) {
        int n = n0 + i;
        int r = (mode == 0) ? n
              : (n < 2048) ? ((n >> 3) << 4) + (n & 7)
                           : (((n - 2048) >> 3) << 4) + 8 + ((n - 2048) & 7);
        out[(size_t)r * K + k0 + tx32] = __float2bfloat16_rn(t[tx32][i]);
    }
}

// ---------------- LayerNorm (bf16 out) ---------------------------------------
__global__ void ln_kernel(const float* __restrict__ X, const float* __restrict__ w,
                          const float* __restrict__ b, bf16* __restrict__ Y) {
    int row = blockIdx.x;
    const float4* x4 = (const float4*)(X + (size_t)row * DMODEL);
    int tid = threadIdx.x;
    float4 v = x4[tid];
    float s  = v.x + v.y + v.z + v.w;
    float ss = v.x * v.x + v.y * v.y + v.z * v.z + v.w * v.w;
#pragma unroll
    for (int o = 16; o > 0; o >>= 1) {
        s  += __shfl_xor_sync(0xffffffffu, s,  o);
        ss += __shfl_xor_sync(0xffffffffu, ss, o);
    }
    __shared__ float sm_s[8], sm_ss[8];
    int wid = tid >> 5, lid = tid & 31;
    if (lid == 0) { sm_s[wid] = s; sm_ss[wid] = ss; }
    __syncthreads();
    if (tid == 0) {
        float ts = 0.f, tss = 0.f;
#pragma unroll
        for (int i = 0; i < 8; i++) { ts += sm_s[i]; tss += sm_ss[i]; }
        sm_s[0] = ts; sm_ss[0] = tss;
    }
    __syncthreads();
    float mean = sm_s[0] * (1.0f / DMODEL);
    float var  = sm_ss[0] * (1.0f / DMODEL) - mean * mean;
    float inv  = rsqrtf(var + 1e-5f);
    float4 w4 = ((const float4*)w)[tid];
    float4 b4 = ((const float4*)b)[tid];
    bf16 h[4];
    h[0] = __float2bfloat16_rn((v.x - mean) * inv * w4.x + b4.x);
    h[1] = __float2bfloat16_rn((v.y - mean) * inv * w4.y + b4.y);
    h[2] = __float2bfloat16_rn((v.z - mean) * inv * w4.z + b4.z);
    h[3] = __float2bfloat16_rn((v.w - mean) * inv * w4.w + b4.w);
    *(uint2*)(Y + (size_t)row * DMODEL + tid * 4) = *(uint2*)h;
}

// ---------------- RoPE (in place on packed QKV) ------------------------------
__global__ void rope_kernel(bf16* __restrict__ QKV) {
    int idx = blockIdx.x * 256 + threadIdx.x;
    if (idx >= TOK * NH * 32) return;
    int i = idx & 31;
    int tokh = idx >> 5;
    int tok = tokh >> 4, h = tokh & 15;
    int m = tok & (MSEQ - 1);
    float invf = 1.0f / powf(10000.0f, (float)(2 * i) * (1.0f / 64.0f));
    float ang = (float)m * invf;
    float s, c;
    sincosf(ang, &s, &c);
    size_t off = (size_t)tok * QKVS + h * 64 + i;
    float q1 = __bfloat162float(QKV[off]), q2 = __bfloat162float(QKV[off + 32]);
    QKV[off]      = __float2bfloat16_rn(q1 * c - q2 * s);
    QKV[off + 32] = __float2bfloat16_rn(q2 * c + q1 * s);
    size_t ko = off + 1024;
    float k1 = __bfloat162float(QKV[ko]), k2 = __bfloat162float(QKV[ko + 32]);
    QKV[ko]      = __float2bfloat16_rn(k1 * c - k2 * s);
    QKV[ko + 32] = __float2bfloat16_rn(k2 * c + k1 * s);
}

// ---------------- Flash attention (bf16 HMMA, FA2) ---------------------------
#define FSM_K 18432
#define FSM_V (18432 + 2 * 9216)
#define FSM_BIAS (18432 + 4 * 9216)
#define FLASHB_SMEM (FSM_BIAS + MSEQ * 4)
#define SCALE_L2E 0.18033688011112042f   // 0.125 * log2(e)

__global__ void __launch_bounds__(256)
flashb_kernel(const bf16* __restrict__ QKV, const int* __restrict__ mask,
              bf16* __restrict__ Og) {
    extern __shared__ char smc[];
    const uint32_t Qsu = s2u(smc);
    const uint32_t Ksu[2] = { s2u(smc) + FSM_K, s2u(smc) + FSM_K + 9216 };
    const uint32_t Vsu[2] = { s2u(smc) + FSM_V, s2u(smc) + FSM_V + 9216 };
    float* sBias = (float*)(smc + FSM_BIAS);
    const int tid = threadIdx.x, wid = tid >> 5, lane = tid & 31, g = lane >> 3;
    const int qt = blockIdx.x, h = blockIdx.y, b = blockIdx.z;
    const size_t base = ((size_t)b * MSEQ) * QKVS + h * DH;
    const bf16* Qp = QKV + base + (size_t)qt * 128 * QKVS;
    const bf16* Kp = QKV + base + 1024;
    const bf16* Vp = QKV + base + 2048;
    const int* mp = mask + b * MSEQ;

#pragma unroll
    for (int i = 0; i < 4; i++) {
        int id = tid + i * 256;
        int r = id >> 3, c = id & 7;
        cp16(Qsu + r * 144 + c * 16, Qp + (size_t)r * QKVS + c * 8);
    }
    CP_COMMIT();

    for (int i = tid; i < MSEQ; i += 256)
        sBias[i] = mp[i] ? 0.f : -1e30f;

    auto loadKV = [&](int kt, int buf) {
        const bf16* K0 = Kp + (size_t)kt * 64 * QKVS;
        const bf16* V0 = Vp + (size_t)kt * 64 * QKVS;
#pragma unroll
        for (int i = 0; i < 2; i++) {
            int id = tid + i * 256;
            int r = id >> 3, c = id & 7;
            cp16(Ksu[buf] + r * 144 + c * 16, K0 + (size_t)r * QKVS + c * 8);
            cp16(Vsu[buf] + r * 144 + c * 16, V0 + (size_t)r * QKVS + c * 8);
        }
        CP_COMMIT();
    };
    loadKV(0, 0);
    loadKV(1, 1);

    uint32_t aq[4][4];
    float o[8][4];
    float m0 = -1e30f, m1 = -1e30f, l0 = 0.f, l1 = 0.f;
#pragma unroll
    for (int nj = 0; nj < 8; nj++)
#pragma unroll
        for (int q = 0; q < 4; q++) o[nj][q] = 0.f;

    const int NT = MSEQ / 64;
    for (int kt = 0; kt < NT; kt++) {
        if (kt + 1 < NT) { CP_WAIT(1); } else { CP_WAIT(0); }
        __syncthreads();
        if (kt == 0) {
#pragma unroll
            for (int ks = 0; ks < 4; ks++) {
                int r = wid * 16 + (lane & 7) + ((g & 1) << 3);
                int cc = ks * 2 + (g >> 1);
                ldsm4(aq[ks][0], aq[ks][1], aq[ks][2], aq[ks][3],
                      Qsu + r * 144 + cc * 16);
            }
        }
        const int buf = kt & 1;

        float s[8][4];
#pragma unroll
        for (int ni = 0; ni < 8; ni++)
#pragma unroll
            for (int q = 0; q < 4; q++) s[ni][q] = 0.f;
#pragma unroll
        for (int ks = 0; ks < 4; ks++) {
            uint32_t bk[8][2];
#pragma unroll
            for (int np = 0; np < 4; np++) {
                int r = np * 16 + (lane & 7) + ((g >> 1) << 3);
                int cc = ks * 2 + (g & 1);
                ldsm4(bk[np * 2][0], bk[np * 2][1], bk[np * 2 + 1][0], bk[np * 2 + 1][1],
                      Ksu[buf] + r * 144 + cc * 16);
            }
#pragma unroll
            for (int ni = 0; ni < 8; ni++)
                mma16816(s[ni], aq[ks], bk[ni]);
        }

        float mx0 = -1e30f, mx1 = -1e30f;
#pragma unroll
        for (int ni = 0; ni < 8; ni++) {
            int col = kt * 64 + ni * 8 + (lane & 3) * 2;
            float2 bb = *(float2*)&sBias[col];
            s[ni][0] = s[ni][0] * SCALE_L2E + bb.x;
            s[ni][1] = s[ni][1] * SCALE_L2E + bb.y;
            s[ni][2] = s[ni][2] * SCALE_L2E + bb.x;
            s[ni][3] = s[ni][3] * SCALE_L2E + bb.y;
            mx0 = fmaxf(mx0, fmaxf(s[ni][0], s[ni][1]));
            mx1 = fmaxf(mx1, fmaxf(s[ni][2], s[ni][3]));
        }
        mx0 = fmaxf(mx0, __shfl_xor_sync(0xffffffffu, mx0, 1));
        mx0 = fmaxf(mx0, __shfl_xor_sync(0xffffffffu, mx0, 2));
        mx1 = fmaxf(mx1, __shfl_xor_sync(0xffffffffu, mx1, 1));
        mx1 = fmaxf(mx1, __shfl_xor_sync(0xffffffffu, mx1, 2));
        float mn0 = fmaxf(m0, mx0), mn1 = fmaxf(m1, mx1);
        float al0 = ex2(m0 - mn0), al1 = ex2(m1 - mn1);
        m0 = mn0; m1 = mn1;
        float sum0 = 0.f, sum1 = 0.f;
#pragma unroll
        for (int ni = 0; ni < 8; ni++) {
            s[ni][0] = ex2(s[ni][0] - mn0);
            s[ni][1] = ex2(s[ni][1] - mn0);
            s[ni][2] = ex2(s[ni][2] - mn1);
            s[ni][3] = ex2(s[ni][3] - mn1);
            sum0 += s[ni][0] + s[ni][1];
            sum1 += s[ni][2] + s[ni][3];
        }
        l0 = l0 * al0 + sum0;
        l1 = l1 * al1 + sum1;
#pragma unroll
        for (int nj = 0; nj < 8; nj++) {
            o[nj][0] *= al0; o[nj][1] *= al0;
            o[nj][2] *= al1; o[nj][3] *= al1;
        }

#pragma unroll
        for (int ks = 0; ks < 4; ks++) {
            uint32_t ap[4];
            ap[0] = packbf(s[2 * ks][0], s[2 * ks][1]);
            ap[1] = packbf(s[2 * ks][2], s[2 * ks][3]);
            ap[2] = packbf(s[2 * ks + 1][0], s[2 * ks + 1][1]);
            ap[3] = packbf(s[2 * ks + 1][2], s[2 * ks + 1][3]);
            uint32_t bv[8][2];
#pragma unroll
            for (int pr = 0; pr < 4; pr++) {
                int r = ks * 16 + (lane & 7) + ((g & 1) << 3);
                int c = pr * 16 + ((g >> 1) << 3);
                ldsm4t(bv[pr * 2][0], bv[pr * 2][1], bv[pr * 2 + 1][0], bv[pr * 2 + 1][1],
                       Vsu[buf] + r * 144 + c * 2);
            }
#pragma unroll
            for (int nj = 0; nj < 8; nj++)
                mma16816(o[nj], ap, bv[nj]);
        }
        __syncthreads();
        if (kt + 2 < NT) loadKV(kt + 2, buf);
    }

    l0 += __shfl_xor_sync(0xffffffffu, l0, 1);
    l0 += __shfl_xor_sync(0xffffffffu, l0, 2);
    l1 += __shfl_xor_sync(0xffffffffu, l1, 1);
    l1 += __shfl_xor_sync(0xffffffffu, l1, 2);
    float inv0 = 1.0f / l0, inv1 = 1.0f / l1;

    const size_t obase = ((size_t)b * MSEQ) * DMODEL + h * DH;
    const int rlo = qt * 128 + wid * 16 + (lane >> 2);
    bf16* Ob = Og + obase;
#pragma unroll
    for (int nj = 0; nj < 8; nj++) {
        int col = nj * 8 + (lane & 3) * 2;
        *(uint32_t*)&Ob[(size_t)rlo * DMODEL + col] = packbf(o[nj][0] * inv0, o[nj][1] * inv0);
        *(uint32_t*)&Ob[(size_t)(rlo + 8) * DMODEL + col] = packbf(o[nj][2] * inv1, o[nj][3] * inv1);
    }
}

// ---------------- launch -----------------------------------------------------
extern "C" void kernel_launch(void* const* d_in, const int* in_sizes, int n_in,
                              void* d_out, int out_size) {
    const float* x    = (const float*)d_in[0];
    const int*   mask = (const int*)  d_in[1];
    const float* ln1w = (const float*)d_in[2];
    const float* ln1b = (const float*)d_in[3];
    const float* ln2w = (const float*)d_in[4];
    const float* ln2b = (const float*)d_in[5];
    const float* Uq   = (const float*)d_in[6];
    const float* Uk   = (const float*)d_in[7];
    const float* Uv   = (const float*)d_in[8];
    const float* Vq   = (const float*)d_in[9];
    const float* Vk   = (const float*)d_in[10];
    const float* Vv   = (const float*)d_in[11];
    const float* bq   = (const float*)d_in[12];
    const float* bk   = (const float*)d_in[13];
    const float* bv   = (const float*)d_in[14];
    const float* Wo   = (const float*)d_in[15];
    const float* Wob  = (const float*)d_in[16];
    const float* U1   = (const float*)d_in[17];
    const float* V1   = (const float*)d_in[18];
    const float* b1   = (const float*)d_in[19];
    const float* U2   = (const float*)d_in[20];
    const float* V2   = (const float*)d_in[21];
    const float* b2   = (const float*)d_in[22];
    float* out = (float*)d_out;

    float *x1, *bqkv;
    bf16 *xnb, *Pb, *QKVb, *AOb, *Gb, *Tb;
    bf16 *wUqkv, *wVqkv, *wWo, *wU1, *wV1, *wU2, *wV2;
    cudaGetSymbolAddress((void**)&x1,   g_x1);
    cudaGetSymbolAddress((void**)&bqkv, g_bqkv);
    cudaGetSymbolAddress((void**)&xnb,  g_xnb);
    cudaGetSymbolAddress((void**)&Pb,   g_Pb);
    cudaGetSymbolAddress((void**)&QKVb, g_QKV);
    cudaGetSymbolAddress((void**)&AOb,  g_AOb);
    cudaGetSymbolAddress((void**)&Gb,   g_Gb);
    cudaGetSymbolAddress((void**)&Tb,   g_Tb);
    cudaGetSymbolAddress((void**)&wUqkv, w_Uqkv);
    cudaGetSymbolAddress((void**)&wVqkv, w_Vqkv);
    cudaGetSymbolAddress((void**)&wWo, w_Wo);
    cudaGetSymbolAddress((void**)&wU1, w_U1);
    cudaGetSymbolAddress((void**)&wV1, w_V1);
    cudaGetSymbolAddress((void**)&wU2, w_U2);
    cudaGetSymbolAddress((void**)&wV2, w_V2);

    cudaFuncSetAttribute(flashb_kernel, cudaFuncAttributeMaxDynamicSharedMemorySize,
                         FLASHB_SMEM);
    cudaFuncSetAttribute(mma_gemm<false, false, true, false, false>,
                         cudaFuncAttributeMaxDynamicSharedMemorySize, GEMM_SMEM);
    cudaFuncSetAttribute(mma_gemm<true, false, true, false, true>,
                         cudaFuncAttributeMaxDynamicSharedMemorySize, GEMM_SMEM);
    cudaFuncSetAttribute(mma_gemm<true, true, false, false, false>,
                         cudaFuncAttributeMaxDynamicSharedMemorySize, GEMM_SMEM);
    cudaFuncSetAttribute(mma_gemm<true, false, false, true, false>,
                         cudaFuncAttributeMaxDynamicSharedMemorySize, GEMM_SMEM);

    // ---- merged weight prep (1 launch) ----
    prep_kernel<<<6657, 256>>>(Uq, Uk, Uv, Vq, Vk, Vv, Wo, U1, V1, U2, V2,
                               bq, bk, bv,
                               wUqkv, wVqkv, wWo, wU1, wV1, wU2, wV2, bqkv);

    // ---- forward ----
    ln_kernel<<<TOK, 256>>>(x, ln1w, ln1b, xnb);

    mma_gemm<false, false, true, false, false><<<dim3(3, TOK / 128), 256, GEMM_SMEM>>>(
        xnb, wUqkv, nullptr, nullptr, nullptr, Pb, 1024, 1024, 768);
    mma_gemm<true, false, true, false, true><<<dim3(12, TOK / 128), 256, GEMM_SMEM>>>(
        Pb, wVqkv, bqkv, nullptr, nullptr, QKVb, 256, 768, QKVS);

    rope_kernel<<<(TOK * NH * 32) / 256, 256>>>(QKVb);
    flashb_kernel<<<dim3(MSEQ / 128, NH, NB), 256, FLASHB_SMEM>>>(QKVb, mask, AOb);

    mma_gemm<true, true, false, false, false><<<dim3(4, TOK / 128), 256, GEMM_SMEM>>>(
        AOb, wWo, Wob, x, x1, nullptr, 1024, 1024, 1024);

    ln_kernel<<<TOK, 256>>>(x1, ln2w, ln2b, xnb);

    mma_gemm<false, false, true, false, false><<<dim3(2, TOK / 128), 256, GEMM_SMEM>>>(
        xnb, wU1, nullptr, nullptr, nullptr, Pb, 1024, 1024, 512);
    mma_gemm<true, false, false, true, false><<<dim3(16, TOK / 128), 256, GEMM_SMEM>>>(
        Pb, wV1, b1, nullptr, nullptr, Gb, 512, 512, 2048);
    mma_gemm<false, false, true, false, false><<<dim3(2, TOK / 128), 256, GEMM_SMEM>>>(
        Gb, wU2, nullptr, nullptr, nullptr, Tb, 2048, 2048, 512);
    mma_gemm<true, true, false, false, false><<<dim3(4, TOK / 128), 256, GEMM_SMEM>>>(
        Tb, wV2, b2, x1, out, nullptr, 512, 512, 1024);
}

// round 13
// speedup vs baseline: 1.0127x; 1.0127x over previous
#include <cuda_runtime.h>
#include <cuda_bf16.h>
#include <math.h>
#include <stdint.h>

// ---------------- problem constants ----------------
#define TOK    8192
#define DMODEL 1024
#define NH     16
#define DH     64
#define MSEQ   2048
#define NB     4
#define QKVS   3072

typedef __nv_bfloat16 bf16;

// ---------------- scratch ----------------------------------------------------
__device__ float g_x1 [TOK * DMODEL];
__device__ float g_bqkv[3072];

__device__ bf16 g_xnb [TOK * DMODEL];
__device__ bf16 g_Pb  [TOK * 768];
__device__ bf16 g_QKV [TOK * QKVS];
__device__ bf16 g_AOb [TOK * DMODEL];
__device__ bf16 g_Gb  [TOK * 2048];
__device__ bf16 g_Tb  [TOK * 512];

// bf16 weights, [N,K] K-major
__device__ bf16 w_Uqkv[768 * 1024];
__device__ bf16 w_Vqkv[3072 * 256];
__device__ bf16 w_Wo[1024 * 1024];
__device__ bf16 w_U1[512 * 1024];
__device__ bf16 w_V1[4096 * 512];       // geglu-interleaved rows
__device__ bf16 w_U2[512 * 2048];
__device__ bf16 w_V2[1024 * 512];

// ---------------- asm helpers ------------------------------------------------
__device__ __forceinline__ uint32_t s2u(const void* p) {
    uint32_t a;
    asm("{ .reg .u64 t; cvta.to.shared.u64 t, %1; cvt.u32.u64 %0, t; }" : "=r"(a) : "l"(p));
    return a;
}
__device__ __forceinline__ void cp16(uint32_t saddr, const void* gptr) {
    asm volatile("cp.async.cg.shared.global [%0], [%1], 16;" :: "r"(saddr), "l"(gptr));
}
#define CP_COMMIT() asm volatile("cp.async.commit_group;" ::: "memory")
#define CP_WAIT(n)  asm volatile("cp.async.wait_group %0;" :: "n"(n) : "memory")

__device__ __forceinline__ void ldsm4(uint32_t& r0, uint32_t& r1, uint32_t& r2,
                                      uint32_t& r3, uint32_t addr) {
    asm volatile("ldmatrix.sync.aligned.m8n8.x4.shared.b16 {%0,%1,%2,%3}, [%4];"
                 : "=r"(r0), "=r"(r1), "=r"(r2), "=r"(r3) : "r"(addr));
}
__device__ __forceinline__ void ldsm4t(uint32_t& r0, uint32_t& r1, uint32_t& r2,
                                       uint32_t& r3, uint32_t addr) {
    asm volatile("ldmatrix.sync.aligned.m8n8.x4.trans.shared.b16 {%0,%1,%2,%3}, [%4];"
                 : "=r"(r0), "=r"(r1), "=r"(r2), "=r"(r3) : "r"(addr));
}
__device__ __forceinline__ void mma16816(float* d, const uint32_t* a, const uint32_t* b) {
    asm volatile(
        "mma.sync.aligned.m16n8k16.row.col.f32.bf16.bf16.f32 "
        "{%0,%1,%2,%3}, {%4,%5,%6,%7}, {%8,%9}, {%0,%1,%2,%3};"
        : "+f"(d[0]), "+f"(d[1]), "+f"(d[2]), "+f"(d[3])
        : "r"(a[0]), "r"(a[1]), "r"(a[2]), "r"(a[3]), "r"(b[0]), "r"(b[1]));
}
__device__ __forceinline__ uint32_t packbf(float lo, float hi) {
    uint32_t d;
    asm("cvt.rn.bf16x2.f32 %0, %1, %2;" : "=r"(d) : "f"(hi), "f"(lo));
    return d;
}
__device__ __forceinline__ float ex2(float x) {
    float r;
    asm("ex2.approx.f32 %0, %1;" : "=f"(r) : "f"(x));
    return r;
}
__device__ __forceinline__ float gelu_t(float a) {
    float inner = 0.7978845608028654f * (a + 0.044715f * a * a * a);
    return 0.5f * a * (1.0f + tanhf(inner));
}
// full 8-way swizzle for 128B rows (BK=64 bf16)
#define SWZ64(r, cc) ((uint32_t)((r) * 128 + (((cc) ^ ((r) & 7)) << 4)))

// ---------------- HMMA GEMM (R9 config): 128x128, 8 warps 64x32, BK=64 -------
#define GEMM_SMEM (3 * 2 * 128 * 64 * 2)
template<bool HASBIAS, bool HASRES, bool OUTBF16, bool GEGLU, bool QKV>
__global__ void __launch_bounds__(256, 2)
mma_gemm(const bf16* __restrict__ A, const bf16* __restrict__ B,
         const float* __restrict__ bias, const float* __restrict__ res,
         float* __restrict__ Cf, bf16* __restrict__ Cb, int K, int lda, int J) {
    extern __shared__ char gsm[];
    const int tid = threadIdx.x;
    const int wid = tid >> 5, lane = tid & 31;
    const int g = lane >> 3;
    const int bm = blockIdx.y * 128, bn = blockIdx.x * 128;
    const int wm = wid >> 2;
    const int wn = wid & 3;
    uint32_t sAb[3], sBb[3];
#pragma unroll
    for (int i = 0; i < 3; i++) {
        sAb[i] = s2u(gsm) + i * 32768;
        sBb[i] = s2u(gsm) + i * 32768 + 16384;
    }

    const bf16* Ag = A + (size_t)bm * lda + (QKV ? (bn >> 10) * 256 : 0);
    const bf16* Bg = B + (size_t)bn * K;

    auto load = [&](int c, int buf) {
        int k0 = c * 64;
#pragma unroll
        for (int i = 0; i < 4; i++) {
            int v = tid + i * 256;
            int r = v >> 3, cc = v & 7;
            uint32_t so = SWZ64(r, cc);
            cp16(sAb[buf] + so, Ag + (size_t)r * lda + k0 + cc * 8);
            cp16(sBb[buf] + so, Bg + (size_t)r * K + k0 + cc * 8);
        }
        CP_COMMIT();
    };

    float acc[4][4][4];
#pragma unroll
    for (int mi = 0; mi < 4; mi++)
#pragma unroll
        for (int ni = 0; ni < 4; ni++)
#pragma unroll
            for (int q = 0; q < 4; q++) acc[mi][ni][q] = 0.f;

    const int NC = K / 64;
    load(0, 0);
    if (NC > 1) load(1, 1);

    int bcur = 0, bpre = 2;
    for (int c = 0; c < NC; c++) {
        if (c + 1 < NC) { CP_WAIT(1); } else { CP_WAIT(0); }
        __syncthreads();
        if (c + 2 < NC) load(c + 2, bpre);
        const int buf = bcur;
#pragma unroll
        for (int ks = 0; ks < 4; ks++) {
            uint32_t a[4][4], b[4][2];
#pragma unroll
            for (int mi = 0; mi < 4; mi++) {
                int r = wm * 64 + mi * 16 + (lane & 7) + ((g & 1) << 3);
                int cc = ks * 2 + (g >> 1);
                ldsm4(a[mi][0], a[mi][1], a[mi][2], a[mi][3], sAb[buf] + SWZ64(r, cc));
            }
#pragma unroll
            for (int pi = 0; pi < 2; pi++) {
                int r = wn * 32 + pi * 16 + (lane & 7) + ((g >> 1) << 3);
                int cc = ks * 2 + (g & 1);
                ldsm4(b[pi * 2][0], b[pi * 2][1], b[pi * 2 + 1][0], b[pi * 2 + 1][1],
                      sBb[buf] + SWZ64(r, cc));
            }
#pragma unroll
            for (int mi = 0; mi < 4; mi++)
#pragma unroll
                for (int ni = 0; ni < 4; ni++)
                    mma16816(acc[mi][ni], a[mi], b[ni]);
        }
        bcur = (bcur == 2) ? 0 : bcur + 1;
        bpre = (bpre == 2) ? 0 : bpre + 1;
    }

    if (GEGLU) {
#pragma unroll
        for (int mi = 0; mi < 4; mi++) {
#pragma unroll
            for (int half = 0; half < 2; half++) {
                int row = bm + wm * 64 + mi * 16 + (lane >> 2) + half * 8;
#pragma unroll
                for (int ni = 0; ni < 4; ni += 2) {
                    int pcb = bn + wn * 32 + ni * 8;
                    int dc = pcb / 2 + (lane & 3) * 2;
                    float h1a = acc[mi][ni][half * 2 + 0];
                    float h1b = acc[mi][ni][half * 2 + 1];
                    float h2a = acc[mi][ni + 1][half * 2 + 0];
                    float h2b = acc[mi][ni + 1][half * 2 + 1];
                    if (HASBIAS) {
                        h1a += bias[dc];        h1b += bias[dc + 1];
                        h2a += bias[2048 + dc]; h2b += bias[2048 + dc + 1];
                    }
                    float g0 = gelu_t(h1a) * h2a;
                    float g1 = gelu_t(h1b) * h2b;
                    *(uint32_t*)&Cb[(size_t)row * 2048 + dc] = packbf(g0, g1);
                }
            }
        }
        return;
    }

#pragma unroll
    for (int mi = 0; mi < 4; mi++) {
#pragma unroll
        for (int half = 0; half < 2; half++) {
            int row = bm + wm * 64 + mi * 16 + (lane >> 2) + half * 8;
#pragma unroll
            for (int ni = 0; ni < 4; ni++) {
                int col = bn + wn * 32 + ni * 8 + (lane & 3) * 2;
                float v0 = acc[mi][ni][half * 2 + 0];
                float v1 = acc[mi][ni][half * 2 + 1];
                if (HASBIAS) { v0 += bias[col]; v1 += bias[col + 1]; }
                if (HASRES) {
                    const float2 rv = *(const float2*)&res[(size_t)row * J + col];
                    v0 += rv.x; v1 += rv.y;
                }
                if (OUTBF16) {
                    *(uint32_t*)&Cb[(size_t)row * J + col] = packbf(v0, v1);
                } else {
                    *(float2*)&Cf[(size_t)row * J + col] = make_float2(v0, v1);
                }
            }
        }
    }
}

// ---------------- merged weight prep ------------------------------------------
__global__ void __launch_bounds__(256)
prep_kernel(const float* __restrict__ Uq, const float* __restrict__ Uk,
            const float* __restrict__ Uv, const float* __restrict__ Vq,
            const float* __restrict__ Vk, const float* __restrict__ Vv,
            const float* __restrict__ Wo, const float* __restrict__ U1,
            const float* __restrict__ V1, const float* __restrict__ U2,
            const float* __restrict__ V2,
            const float* __restrict__ bq, const float* __restrict__ bk,
            const float* __restrict__ bv,
            bf16* __restrict__ wUqkv, bf16* __restrict__ wVqkv,
            bf16* __restrict__ wWo, bf16* __restrict__ wU1,
            bf16* __restrict__ wV1, bf16* __restrict__ wU2, bf16* __restrict__ wV2,
            float* __restrict__ bqkv) {
    __shared__ float t[32][33];
    int bid = blockIdx.x;
    const int tx32 = threadIdx.x & 31, ty8 = threadIdx.x >> 5;
    const float* in; bf16* out;
    int K, N, mode = 0;
    if (bid < 768) {
        int j = bid / 256; bid &= 255;
        in = (j == 0) ? Uq : (j == 1) ? Uk : Uv;
        out = wUqkv + j * 256 * 1024; K = 1024; N = 256;
    } else if (bid < 1536) {
        int j = (bid - 768) / 256; bid = (bid - 768) & 255;
        in = (j == 0) ? Vq : (j == 1) ? Vk : Vv;
        out = wVqkv + j * 1024 * 256; K = 256; N = 1024;
    } else if (bid < 2048) { in = U1; out = wU1; K = 1024; N = 512;  bid -= 1536; }
    else if (bid < 2560)   { in = V2; out = wV2; K = 512;  N = 1024; bid -= 2048; }
    else if (bid < 3584)   { in = U2; out = wU2; K = 2048; N = 512;  bid -= 2560; }
    else if (bid < 5632)   { in = V1; out = wV1; K = 512;  N = 4096; bid -= 3584; mode = 1; }
    else if (bid < 6656) {
        size_t base = (size_t)(bid - 5632) * 1024 + threadIdx.x * 4;
        float4 v = *(const float4*)(Wo + base);
        bf16 h[4];
        h[0] = __float2bfloat16_rn(v.x); h[1] = __float2bfloat16_rn(v.y);
        h[2] = __float2bfloat16_rn(v.z); h[3] = __float2bfloat16_rn(v.w);
        *(uint2*)(wWo + base) = *(uint2*)h;
        return;
    } else {
        for (int i = threadIdx.x; i < 1024; i += 256) {
            bqkv[i]        = bq[i];
            bqkv[1024 + i] = bk[i];
            bqkv[2048 + i] = bv[i];
        }
        return;
    }
    const int nt = N / 32;
    int k0 = (bid / nt) * 32, n0 = (bid % nt) * 32;
    for (int i = ty8; i < 32; i += 8)
        t[i][tx32] = in[(size_t)(k0 + i) * N + n0 + tx32];
    __syncthreads();
    for (int i = ty8; i < 32; i += 8) {
        int n = n0 + i;
        int r = (mode == 0) ? n
              : (n < 2048) ? ((n >> 3) << 4) + (n & 7)
                           : (((n - 2048) >> 3) << 4) + 8 + ((n - 2048) & 7);
        out[(size_t)r * K + k0 + tx32] = __float2bfloat16_rn(t[tx32][i]);
    }
}

// ---------------- LayerNorm (bf16 out) ---------------------------------------
__global__ void ln_kernel(const float* __restrict__ X, const float* __restrict__ w,
                          const float* __restrict__ b, bf16* __restrict__ Y) {
    int row = blockIdx.x;
    const float4* x4 = (const float4*)(X + (size_t)row * DMODEL);
    int tid = threadIdx.x;
    float4 v = x4[tid];
    float s  = v.x + v.y + v.z + v.w;
    float ss = v.x * v.x + v.y * v.y + v.z * v.z + v.w * v.w;
#pragma unroll
    for (int o = 16; o > 0; o >>= 1) {
        s  += __shfl_xor_sync(0xffffffffu, s,  o);
        ss += __shfl_xor_sync(0xffffffffu, ss, o);
    }
    __shared__ float sm_s[8], sm_ss[8];
    int wid = tid >> 5, lid = tid & 31;
    if (lid == 0) { sm_s[wid] = s; sm_ss[wid] = ss; }
    __syncthreads();
    if (tid == 0) {
        float ts = 0.f, tss = 0.f;
#pragma unroll
        for (int i = 0; i < 8; i++) { ts += sm_s[i]; tss += sm_ss[i]; }
        sm_s[0] = ts; sm_ss[0] = tss;
    }
    __syncthreads();
    float mean = sm_s[0] * (1.0f / DMODEL);
    float var  = sm_ss[0] * (1.0f / DMODEL) - mean * mean;
    float inv  = rsqrtf(var + 1e-5f);
    float4 w4 = ((const float4*)w)[tid];
    float4 b4 = ((const float4*)b)[tid];
    bf16 h[4];
    h[0] = __float2bfloat16_rn((v.x - mean) * inv * w4.x + b4.x);
    h[1] = __float2bfloat16_rn((v.y - mean) * inv * w4.y + b4.y);
    h[2] = __float2bfloat16_rn((v.z - mean) * inv * w4.z + b4.z);
    h[3] = __float2bfloat16_rn((v.w - mean) * inv * w4.w + b4.w);
    *(uint2*)(Y + (size_t)row * DMODEL + tid * 4) = *(uint2*)h;
}

// ---------------- RoPE (in place on packed QKV) ------------------------------
__global__ void rope_kernel(bf16* __restrict__ QKV) {
    int idx = blockIdx.x * 256 + threadIdx.x;
    if (idx >= TOK * NH * 32) return;
    int i = idx & 31;
    int tokh = idx >> 5;
    int tok = tokh >> 4, h = tokh & 15;
    int m = tok & (MSEQ - 1);
    float invf = 1.0f / powf(10000.0f, (float)(2 * i) * (1.0f / 64.0f));
    float ang = (float)m * invf;
    float s, c;
    sincosf(ang, &s, &c);
    size_t off = (size_t)tok * QKVS + h * 64 + i;
    float q1 = __bfloat162float(QKV[off]), q2 = __bfloat162float(QKV[off + 32]);
    QKV[off]      = __float2bfloat16_rn(q1 * c - q2 * s);
    QKV[off + 32] = __float2bfloat16_rn(q2 * c + q1 * s);
    size_t ko = off + 1024;
    float k1 = __bfloat162float(QKV[ko]), k2 = __bfloat162float(QKV[ko + 32]);
    QKV[ko]      = __float2bfloat16_rn(k1 * c - k2 * s);
    QKV[ko + 32] = __float2bfloat16_rn(k2 * c + k1 * s);
}

// ---------------- Flash attention (bf16 HMMA, FA2, 3-buf KV, 1 sync/iter) ----
#define FSM_KV 18432                       // after Q (128*144)
#define KVSTG  18432                       // per stage: K 9216 + V 9216
#define FSM_BIAS (FSM_KV + 3 * KVSTG)
#define FLASHB_SMEM (FSM_BIAS + MSEQ * 4)
#define SCALE_L2E 0.18033688011112042f     // 0.125 * log2(e)

__global__ void __launch_bounds__(256)
flashb_kernel(const bf16* __restrict__ QKV, const int* __restrict__ mask,
              bf16* __restrict__ Og) {
    extern __shared__ char smc[];
    const uint32_t Qsu = s2u(smc);
    uint32_t Ksu[3], Vsu[3];
#pragma unroll
    for (int i = 0; i < 3; i++) {
        Ksu[i] = s2u(smc) + FSM_KV + i * KVSTG;
        Vsu[i] = s2u(smc) + FSM_KV + i * KVSTG + 9216;
    }
    float* sBias = (float*)(smc + FSM_BIAS);
    const int tid = threadIdx.x, wid = tid >> 5, lane = tid & 31, g = lane >> 3;
    const int qt = blockIdx.x, h = blockIdx.y, b = blockIdx.z;
    const size_t base = ((size_t)b * MSEQ) * QKVS + h * DH;
    const bf16* Qp = QKV + base + (size_t)qt * 128 * QKVS;
    const bf16* Kp = QKV + base + 1024;
    const bf16* Vp = QKV + base + 2048;
    const int* mp = mask + b * MSEQ;

#pragma unroll
    for (int i = 0; i < 4; i++) {
        int id = tid + i * 256;
        int r = id >> 3, c = id & 7;
        cp16(Qsu + r * 144 + c * 16, Qp + (size_t)r * QKVS + c * 8);
    }
    CP_COMMIT();

    for (int i = tid; i < MSEQ; i += 256)
        sBias[i] = mp[i] ? 0.f : -1e30f;

    auto loadKV = [&](int kt, int buf) {
        const bf16* K0 = Kp + (size_t)kt * 64 * QKVS;
        const bf16* V0 = Vp + (size_t)kt * 64 * QKVS;
#pragma unroll
        for (int i = 0; i < 2; i++) {
            int id = tid + i * 256;
            int r = id >> 3, c = id & 7;
            cp16(Ksu[buf] + r * 144 + c * 16, K0 + (size_t)r * QKVS + c * 8);
            cp16(Vsu[buf] + r * 144 + c * 16, V0 + (size_t)r * QKVS + c * 8);
        }
        CP_COMMIT();
    };
    loadKV(0, 0);
    loadKV(1, 1);

    uint32_t aq[4][4];
    float o[8][4];
    float m0 = -1e30f, m1 = -1e30f, l0 = 0.f, l1 = 0.f;
#pragma unroll
    for (int nj = 0; nj < 8; nj++)
#pragma unroll
        for (int q = 0; q < 4; q++) o[nj][q] = 0.f;

    const int NT = MSEQ / 64;
    int bcur = 0, bpre = 2;
    for (int kt = 0; kt < NT; kt++) {
        if (kt + 1 < NT) { CP_WAIT(1); } else { CP_WAIT(0); }
        __syncthreads();
        // 3 buffers: all warps finished reading buffer bpre in iter kt-1,
        // so prefetch into it right after the barrier. One sync per iter.
        if (kt + 2 < NT) loadKV(kt + 2, bpre);
        if (kt == 0) {
#pragma unroll
            for (int ks = 0; ks < 4; ks++) {
                int r = wid * 16 + (lane & 7) + ((g & 1) << 3);
                int cc = ks * 2 + (g >> 1);
                ldsm4(aq[ks][0], aq[ks][1], aq[ks][2], aq[ks][3],
                      Qsu + r * 144 + cc * 16);
            }
        }
        const int buf = bcur;

        float s[8][4];
#pragma unroll
        for (int ni = 0; ni < 8; ni++)
#pragma unroll
            for (int q = 0; q < 4; q++) s[ni][q] = 0.f;
#pragma unroll
        for (int ks = 0; ks < 4; ks++) {
            uint32_t bk[8][2];
#pragma unroll
            for (int np = 0; np < 4; np++) {
                int r = np * 16 + (lane & 7) + ((g >> 1) << 3);
                int cc = ks * 2 + (g & 1);
                ldsm4(bk[np * 2][0], bk[np * 2][1], bk[np * 2 + 1][0], bk[np * 2 + 1][1],
                      Ksu[buf] + r * 144 + cc * 16);
            }
#pragma unroll
            for (int ni = 0; ni < 8; ni++)
                mma16816(s[ni], aq[ks], bk[ni]);
        }

        float mx0 = -1e30f, mx1 = -1e30f;
#pragma unroll
        for (int ni = 0; ni < 8; ni++) {
            int col = kt * 64 + ni * 8 + (lane & 3) * 2;
            float2 bb = *(float2*)&sBias[col];
            s[ni][0] = s[ni][0] * SCALE_L2E + bb.x;
            s[ni][1] = s[ni][1] * SCALE_L2E + bb.y;
            s[ni][2] = s[ni][2] * SCALE_L2E + bb.x;
            s[ni][3] = s[ni][3] * SCALE_L2E + bb.y;
            mx0 = fmaxf(mx0, fmaxf(s[ni][0], s[ni][1]));
            mx1 = fmaxf(mx1, fmaxf(s[ni][2], s[ni][3]));
        }
        mx0 = fmaxf(mx0, __shfl_xor_sync(0xffffffffu, mx0, 1));
        mx0 = fmaxf(mx0, __shfl_xor_sync(0xffffffffu, mx0, 2));
        mx1 = fmaxf(mx1, __shfl_xor_sync(0xffffffffu, mx1, 1));
        mx1 = fmaxf(mx1, __shfl_xor_sync(0xffffffffu, mx1, 2));
        float mn0 = fmaxf(m0, mx0), mn1 = fmaxf(m1, mx1);
        float al0 = ex2(m0 - mn0), al1 = ex2(m1 - mn1);
        m0 = mn0; m1 = mn1;
        float sum0 = 0.f, sum1 = 0.f;
#pragma unroll
        for (int ni = 0; ni < 8; ni++) {
            s[ni][0] = ex2(s[ni][0] - mn0);
            s[ni][1] = ex2(s[ni][1] - mn0);
            s[ni][2] = ex2(s[ni][2] - mn1);
            s[ni][3] = ex2(s[ni][3] - mn1);
            sum0 += s[ni][0] + s[ni][1];
            sum1 += s[ni][2] + s[ni][3];
        }
        l0 = l0 * al0 + sum0;
        l1 = l1 * al1 + sum1;
#pragma unroll
        for (int nj = 0; nj < 8; nj++) {
            o[nj][0] *= al0; o[nj][1] *= al0;
            o[nj][2] *= al1; o[nj][3] *= al1;
        }

#pragma unroll
        for (int ks = 0; ks < 4; ks++) {
            uint32_t ap[4];
            ap[0] = packbf(s[2 * ks][0], s[2 * ks][1]);
            ap[1] = packbf(s[2 * ks][2], s[2 * ks][3]);
            ap[2] = packbf(s[2 * ks + 1][0], s[2 * ks + 1][1]);
            ap[3] = packbf(s[2 * ks + 1][2], s[2 * ks + 1][3]);
            uint32_t bv[8][2];
#pragma unroll
            for (int pr = 0; pr < 4; pr++) {
                int r = ks * 16 + (lane & 7) + ((g & 1) << 3);
                int c = pr * 16 + ((g >> 1) << 3);
                ldsm4t(bv[pr * 2][0], bv[pr * 2][1], bv[pr * 2 + 1][0], bv[pr * 2 + 1][1],
                       Vsu[buf] + r * 144 + c * 2);
            }
#pragma unroll
            for (int nj = 0; nj < 8; nj++)
                mma16816(o[nj], ap, bv[nj]);
        }
        bcur = (bcur == 2) ? 0 : bcur + 1;
        bpre = (bpre == 2) ? 0 : bpre + 1;
    }

    l0 += __shfl_xor_sync(0xffffffffu, l0, 1);
    l0 += __shfl_xor_sync(0xffffffffu, l0, 2);
    l1 += __shfl_xor_sync(0xffffffffu, l1, 1);
    l1 += __shfl_xor_sync(0xffffffffu, l1, 2);
    float inv0 = 1.0f / l0, inv1 = 1.0f / l1;

    const size_t obase = ((size_t)b * MSEQ) * DMODEL + h * DH;
    const int rlo = qt * 128 + wid * 16 + (lane >> 2);
    bf16* Ob = Og + obase;
#pragma unroll
    for (int nj = 0; nj < 8; nj++) {
        int col = nj * 8 + (lane & 3) * 2;
        *(uint32_t*)&Ob[(size_t)rlo * DMODEL + col] = packbf(o[nj][0] * inv0, o[nj][1] * inv0);
        *(uint32_t*)&Ob[(size_t)(rlo + 8) * DMODEL + col] = packbf(o[nj][2] * inv1, o[nj][3] * inv1);
    }
}

// ---------------- launch -----------------------------------------------------
extern "C" void kernel_launch(void* const* d_in, const int* in_sizes, int n_in,
                              void* d_out, int out_size) {
    const float* x    = (const float*)d_in[0];
    const int*   mask = (const int*)  d_in[1];
    const float* ln1w = (const float*)d_in[2];
    const float* ln1b = (const float*)d_in[3];
    const float* ln2w = (const float*)d_in[4];
    const float* ln2b = (const float*)d_in[5];
    const float* Uq   = (const float*)d_in[6];
    const float* Uk   = (const float*)d_in[7];
    const float* Uv   = (const float*)d_in[8];
    const float* Vq   = (const float*)d_in[9];
    const float* Vk   = (const float*)d_in[10];
    const float* Vv   = (const float*)d_in[11];
    const float* bq   = (const float*)d_in[12];
    const float* bk   = (const float*)d_in[13];
    const float* bv   = (const float*)d_in[14];
    const float* Wo   = (const float*)d_in[15];
    const float* Wob  = (const float*)d_in[16];
    const float* U1   = (const float*)d_in[17];
    const float* V1   = (const float*)d_in[18];
    const float* b1   = (const float*)d_in[19];
    const float* U2   = (const float*)d_in[20];
    const float* V2   = (const float*)d_in[21];
    const float* b2   = (const float*)d_in[22];
    float* out = (float*)d_out;

    float *x1, *bqkv;
    bf16 *xnb, *Pb, *QKVb, *AOb, *Gb, *Tb;
    bf16 *wUqkv, *wVqkv, *wWo, *wU1, *wV1, *wU2, *wV2;
    cudaGetSymbolAddress((void**)&x1,   g_x1);
    cudaGetSymbolAddress((void**)&bqkv, g_bqkv);
    cudaGetSymbolAddress((void**)&xnb,  g_xnb);
    cudaGetSymbolAddress((void**)&Pb,   g_Pb);
    cudaGetSymbolAddress((void**)&QKVb, g_QKV);
    cudaGetSymbolAddress((void**)&AOb,  g_AOb);
    cudaGetSymbolAddress((void**)&Gb,   g_Gb);
    cudaGetSymbolAddress((void**)&Tb,   g_Tb);
    cudaGetSymbolAddress((void**)&wUqkv, w_Uqkv);
    cudaGetSymbolAddress((void**)&wVqkv, w_Vqkv);
    cudaGetSymbolAddress((void**)&wWo, w_Wo);
    cudaGetSymbolAddress((void**)&wU1, w_U1);
    cudaGetSymbolAddress((void**)&wV1, w_V1);
    cudaGetSymbolAddress((void**)&wU2, w_U2);
    cudaGetSymbolAddress((void**)&wV2, w_V2);

    cudaFuncSetAttribute(flashb_kernel, cudaFuncAttributeMaxDynamicSharedMemorySize,
                         FLASHB_SMEM);
    cudaFuncSetAttribute(mma_gemm<false, false, true, false, false>,
                         cudaFuncAttributeMaxDynamicSharedMemorySize, GEMM_SMEM);
    cudaFuncSetAttribute(mma_gemm<true, false, true, false, true>,
                         cudaFuncAttributeMaxDynamicSharedMemorySize, GEMM_SMEM);
    cudaFuncSetAttribute(mma_gemm<true, true, false, false, false>,
                         cudaFuncAttributeMaxDynamicSharedMemorySize, GEMM_SMEM);
    cudaFuncSetAttribute(mma_gemm<true, false, false, true, false>,
                         cudaFuncAttributeMaxDynamicSharedMemorySize, GEMM_SMEM);

    // ---- merged weight prep (1 launch) ----
    prep_kernel<<<6657, 256>>>(Uq, Uk, Uv, Vq, Vk, Vv, Wo, U1, V1, U2, V2,
                               bq, bk, bv,
                               wUqkv, wVqkv, wWo, wU1, wV1, wU2, wV2, bqkv);

    // ---- forward ----
    ln_kernel<<<TOK, 256>>>(x, ln1w, ln1b, xnb);

    mma_gemm<false, false, true, false, false><<<dim3(6, TOK / 128), 256, GEMM_SMEM>>>(
        xnb, wUqkv, nullptr, nullptr, nullptr, Pb, 1024, 1024, 768);
    mma_gemm<true, false, true, false, true><<<dim3(24, TOK / 128), 256, GEMM_SMEM>>>(
        Pb, wVqkv, bqkv, nullptr, nullptr, QKVb, 256, 768, QKVS);

    rope_kernel<<<(TOK * NH * 32) / 256, 256>>>(QKVb);
    flashb_kernel<<<dim3(MSEQ / 128, NH, NB), 256, FLASHB_SMEM>>>(QKVb, mask, AOb);

    mma_gemm<true, true, false, false, false><<<dim3(8, TOK / 128), 256, GEMM_SMEM>>>(
        AOb, wWo, Wob, x, x1, nullptr, 1024, 1024, 1024);

    ln_kernel<<<TOK, 256>>>(x1, ln2w, ln2b, xnb);

    mma_gemm<false, false, true, false, false><<<dim3(4, TOK / 128), 256, GEMM_SMEM>>>(
        xnb, wU1, nullptr, nullptr, nullptr, Pb, 1024, 1024, 512);
    mma_gemm<true, false, false, true, false><<<dim3(32, TOK / 128), 256, GEMM_SMEM>>>(
        Pb, wV1, b1, nullptr, nullptr, Gb, 512, 512, 2048);
    mma_gemm<false, false, true, false, false><<<dim3(4, TOK / 128), 256, GEMM_SMEM>>>(
        Gb, wU2, nullptr, nullptr, nullptr, Tb, 2048, 2048, 512);
    mma_gemm<true, true, false, false, false><<<dim3(8, TOK / 128), 256, GEMM_SMEM>>>(
        Tb, wV2, b2, x1, out, nullptr, 512, 512, 1024);
}

// round 16
// speedup vs baseline: 1.0229x; 1.0101x over previous
#include <cuda_runtime.h>
#include <cuda_bf16.h>
#include <math.h>
#include <stdint.h>

// ---------------- problem constants ----------------
#define TOK    8192
#define DMODEL 1024
#define NH     16
#define DH     64
#define MSEQ   2048
#define NB     4
#define QKVS   3072

typedef __nv_bfloat16 bf16;

// ---------------- scratch ----------------------------------------------------
__device__ float g_x1 [TOK * DMODEL];
__device__ float g_bqkv[3072];

__device__ bf16 g_xnb [TOK * DMODEL];
__device__ bf16 g_Pb  [TOK * 768];
__device__ bf16 g_QKV [TOK * QKVS];
__device__ bf16 g_AOb [TOK * DMODEL];
__device__ bf16 g_Gb  [TOK * 2048];
__device__ bf16 g_Tb  [TOK * 512];

// bf16 weights, [N,K] K-major
__device__ bf16 w_Uqkv[768 * 1024];
__device__ bf16 w_Vqkv[3072 * 256];
__device__ bf16 w_Wo[1024 * 1024];
__device__ bf16 w_U1[512 * 1024];
__device__ bf16 w_V1[4096 * 512];       // geglu-interleaved rows
__device__ bf16 w_U2[512 * 2048];
__device__ bf16 w_V2[1024 * 512];

// ---------------- asm helpers ------------------------------------------------
__device__ __forceinline__ uint32_t s2u(const void* p) {
    uint32_t a;
    asm("{ .reg .u64 t; cvta.to.shared.u64 t, %1; cvt.u32.u64 %0, t; }" : "=r"(a) : "l"(p));
    return a;
}
__device__ __forceinline__ void cp16(uint32_t saddr, const void* gptr) {
    asm volatile("cp.async.cg.shared.global [%0], [%1], 16;" :: "r"(saddr), "l"(gptr));
}
#define CP_COMMIT() asm volatile("cp.async.commit_group;" ::: "memory")
#define CP_WAIT(n)  asm volatile("cp.async.wait_group %0;" :: "n"(n) : "memory")

__device__ __forceinline__ void ldsm4(uint32_t& r0, uint32_t& r1, uint32_t& r2,
                                      uint32_t& r3, uint32_t addr) {
    asm volatile("ldmatrix.sync.aligned.m8n8.x4.shared.b16 {%0,%1,%2,%3}, [%4];"
                 : "=r"(r0), "=r"(r1), "=r"(r2), "=r"(r3) : "r"(addr));
}
__device__ __forceinline__ void ldsm4t(uint32_t& r0, uint32_t& r1, uint32_t& r2,
                                       uint32_t& r3, uint32_t addr) {
    asm volatile("ldmatrix.sync.aligned.m8n8.x4.trans.shared.b16 {%0,%1,%2,%3}, [%4];"
                 : "=r"(r0), "=r"(r1), "=r"(r2), "=r"(r3) : "r"(addr));
}
__device__ __forceinline__ void mma16816(float* d, const uint32_t* a, const uint32_t* b) {
    asm volatile(
        "mma.sync.aligned.m16n8k16.row.col.f32.bf16.bf16.f32 "
        "{%0,%1,%2,%3}, {%4,%5,%6,%7}, {%8,%9}, {%0,%1,%2,%3};"
        : "+f"(d[0]), "+f"(d[1]), "+f"(d[2]), "+f"(d[3])
        : "r"(a[0]), "r"(a[1]), "r"(a[2]), "r"(a[3]), "r"(b[0]), "r"(b[1]));
}
__device__ __forceinline__ uint32_t packbf(float lo, float hi) {
    uint32_t d;
    asm("cvt.rn.bf16x2.f32 %0, %1, %2;" : "=r"(d) : "f"(hi), "f"(lo));
    return d;
}
__device__ __forceinline__ float ex2(float x) {
    float r;
    asm("ex2.approx.f32 %0, %1;" : "=f"(r) : "f"(x));
    return r;
}
__device__ __forceinline__ float gelu_t(float a) {
    float inner = 0.7978845608028654f * (a + 0.044715f * a * a * a);
    return 0.5f * a * (1.0f + tanhf(inner));
}
// full 8-way swizzle for 128B rows (BK=64 bf16)
#define SWZ64(r, cc) ((uint32_t)((r) * 128 + (((cc) ^ ((r) & 7)) << 4)))
#define SCALE_L2E 0.18033688011112042f     // 0.125 * log2(e)

// ---------------- HMMA GEMM (R9 config): 128x128, 8 warps 64x32, BK=64 -------
#define GEMM_SMEM (3 * 2 * 128 * 64 * 2)
template<bool HASBIAS, bool HASRES, bool OUTBF16, bool GEGLU, bool QKV>
__global__ void __launch_bounds__(256, 2)
mma_gemm(const bf16* __restrict__ A, const bf16* __restrict__ B,
         const float* __restrict__ bias, const float* __restrict__ res,
         float* __restrict__ Cf, bf16* __restrict__ Cb, int K, int lda, int J) {
    extern __shared__ char gsm[];
    const int tid = threadIdx.x;
    const int wid = tid >> 5, lane = tid & 31;
    const int g = lane >> 3;
    const int bm = blockIdx.y * 128, bn = blockIdx.x * 128;
    const int wm = wid >> 2;
    const int wn = wid & 3;
    uint32_t sAb[3], sBb[3];
#pragma unroll
    for (int i = 0; i < 3; i++) {
        sAb[i] = s2u(gsm) + i * 32768;
        sBb[i] = s2u(gsm) + i * 32768 + 16384;
    }

    const bf16* Ag = A + (size_t)bm * lda + (QKV ? (bn >> 10) * 256 : 0);
    const bf16* Bg = B + (size_t)bn * K;

    auto load = [&](int c, int buf) {
        int k0 = c * 64;
#pragma unroll
        for (int i = 0; i < 4; i++) {
            int v = tid + i * 256;
            int r = v >> 3, cc = v & 7;
            uint32_t so = SWZ64(r, cc);
            cp16(sAb[buf] + so, Ag + (size_t)r * lda + k0 + cc * 8);
            cp16(sBb[buf] + so, Bg + (size_t)r * K + k0 + cc * 8);
        }
        CP_COMMIT();
    };

    float acc[4][4][4];
#pragma unroll
    for (int mi = 0; mi < 4; mi++)
#pragma unroll
        for (int ni = 0; ni < 4; ni++)
#pragma unroll
            for (int q = 0; q < 4; q++) acc[mi][ni][q] = 0.f;

    const int NC = K / 64;
    load(0, 0);
    if (NC > 1) load(1, 1);

    int bcur = 0, bpre = 2;
    for (int c = 0; c < NC; c++) {
        if (c + 1 < NC) { CP_WAIT(1); } else { CP_WAIT(0); }
        __syncthreads();
        if (c + 2 < NC) load(c + 2, bpre);
        const int buf = bcur;
#pragma unroll
        for (int ks = 0; ks < 4; ks++) {
            uint32_t a[4][4], b[4][2];
#pragma unroll
            for (int mi = 0; mi < 4; mi++) {
                int r = wm * 64 + mi * 16 + (lane & 7) + ((g & 1) << 3);
                int cc = ks * 2 + (g >> 1);
                ldsm4(a[mi][0], a[mi][1], a[mi][2], a[mi][3], sAb[buf] + SWZ64(r, cc));
            }
#pragma unroll
            for (int pi = 0; pi < 2; pi++) {
                int r = wn * 32 + pi * 16 + (lane & 7) + ((g >> 1) << 3);
                int cc = ks * 2 + (g & 1);
                ldsm4(b[pi * 2][0], b[pi * 2][1], b[pi * 2 + 1][0], b[pi * 2 + 1][1],
                      sBb[buf] + SWZ64(r, cc));
            }
#pragma unroll
            for (int mi = 0; mi < 4; mi++)
#pragma unroll
                for (int ni = 0; ni < 4; ni++)
                    mma16816(acc[mi][ni], a[mi], b[ni]);
        }
        bcur = (bcur == 2) ? 0 : bcur + 1;
        bpre = (bpre == 2) ? 0 : bpre + 1;
    }

    if (GEGLU) {
#pragma unroll
        for (int mi = 0; mi < 4; mi++) {
#pragma unroll
            for (int half = 0; half < 2; half++) {
                int row = bm + wm * 64 + mi * 16 + (lane >> 2) + half * 8;
#pragma unroll
                for (int ni = 0; ni < 4; ni += 2) {
                    int pcb = bn + wn * 32 + ni * 8;
                    int dc = pcb / 2 + (lane & 3) * 2;
                    float h1a = acc[mi][ni][half * 2 + 0];
                    float h1b = acc[mi][ni][half * 2 + 1];
                    float h2a = acc[mi][ni + 1][half * 2 + 0];
                    float h2b = acc[mi][ni + 1][half * 2 + 1];
                    if (HASBIAS) {
                        h1a += bias[dc];        h1b += bias[dc + 1];
                        h2a += bias[2048 + dc]; h2b += bias[2048 + dc + 1];
                    }
                    float g0 = gelu_t(h1a) * h2a;
                    float g1 = gelu_t(h1b) * h2b;
                    *(uint32_t*)&Cb[(size_t)row * 2048 + dc] = packbf(g0, g1);
                }
            }
        }
        return;
    }

#pragma unroll
    for (int mi = 0; mi < 4; mi++) {
#pragma unroll
        for (int half = 0; half < 2; half++) {
            int row = bm + wm * 64 + mi * 16 + (lane >> 2) + half * 8;
#pragma unroll
            for (int ni = 0; ni < 4; ni++) {
                int col = bn + wn * 32 + ni * 8 + (lane & 3) * 2;
                float v0 = acc[mi][ni][half * 2 + 0];
                float v1 = acc[mi][ni][half * 2 + 1];
                if (HASBIAS) { v0 += bias[col]; v1 += bias[col + 1]; }
                if (HASRES) {
                    const float2 rv = *(const float2*)&res[(size_t)row * J + col];
                    v0 += rv.x; v1 += rv.y;
                }
                if (OUTBF16) {
                    *(uint32_t*)&Cb[(size_t)row * J + col] = packbf(v0, v1);
                } else {
                    *(float2*)&Cf[(size_t)row * J + col] = make_float2(v0, v1);
                }
            }
        }
    }
}

// ---------------- merged weight prep ------------------------------------------
__global__ void __launch_bounds__(256)
prep_kernel(const float* __restrict__ Uq, const float* __restrict__ Uk,
            const float* __restrict__ Uv, const float* __restrict__ Vq,
            const float* __restrict__ Vk, const float* __restrict__ Vv,
            const float* __restrict__ Wo, const float* __restrict__ U1,
            const float* __restrict__ V1, const float* __restrict__ U2,
            const float* __restrict__ V2,
            const float* __restrict__ bq, const float* __restrict__ bk,
            const float* __restrict__ bv,
            bf16* __restrict__ wUqkv, bf16* __restrict__ wVqkv,
            bf16* __restrict__ wWo, bf16* __restrict__ wU1,
            bf16* __restrict__ wV1, bf16* __restrict__ wU2, bf16* __restrict__ wV2,
            float* __restrict__ bqkv) {
    __shared__ float t[32][33];
    int bid = blockIdx.x;
    const int tx32 = threadIdx.x & 31, ty8 = threadIdx.x >> 5;
    const float* in; bf16* out;
    int K, N, mode = 0;
    if (bid < 768) {
        int j = bid / 256; bid &= 255;
        in = (j == 0) ? Uq : (j == 1) ? Uk : Uv;
        out = wUqkv + j * 256 * 1024; K = 1024; N = 256;
    } else if (bid < 1536) {
        int j = (bid - 768) / 256; bid = (bid - 768) & 255;
        in = (j == 0) ? Vq : (j == 1) ? Vk : Vv;
        out = wVqkv + j * 1024 * 256; K = 256; N = 1024;
    } else if (bid < 2048) { in = U1; out = wU1; K = 1024; N = 512;  bid -= 1536; }
    else if (bid < 2560)   { in = V2; out = wV2; K = 512;  N = 1024; bid -= 2048; }
    else if (bid < 3584)   { in = U2; out = wU2; K = 2048; N = 512;  bid -= 2560; }
    else if (bid < 5632)   { in = V1; out = wV1; K = 512;  N = 4096; bid -= 3584; mode = 1; }
    else if (bid < 6656) {
        size_t base = (size_t)(bid - 5632) * 1024 + threadIdx.x * 4;
        float4 v = *(const float4*)(Wo + base);
        bf16 h[4];
        h[0] = __float2bfloat16_rn(v.x); h[1] = __float2bfloat16_rn(v.y);
        h[2] = __float2bfloat16_rn(v.z); h[3] = __float2bfloat16_rn(v.w);
        *(uint2*)(wWo + base) = *(uint2*)h;
        return;
    } else {
        for (int i = threadIdx.x; i < 1024; i += 256) {
            bqkv[i]        = bq[i];
            bqkv[1024 + i] = bk[i];
            bqkv[2048 + i] = bv[i];
        }
        return;
    }
    const int nt = N / 32;
    int k0 = (bid / nt) * 32, n0 = (bid % nt) * 32;
    for (int i = ty8; i < 32; i += 8)
        t[i][tx32] = in[(size_t)(k0 + i) * N + n0 + tx32];
    __syncthreads();
    for (int i = ty8; i < 32; i += 8) {
        int n = n0 + i;
        int r = (mode == 0) ? n
              : (n < 2048) ? ((n >> 3) << 4) + (n & 7)
                           : (((n - 2048) >> 3) << 4) + 8 + ((n - 2048) & 7);
        out[(size_t)r * K + k0 + tx32] = __float2bfloat16_rn(t[tx32][i]);
    }
}

// ---------------- LayerNorm (bf16 out) ---------------------------------------
__global__ void ln_kernel(const float* __restrict__ X, const float* __restrict__ w,
                          const float* __restrict__ b, bf16* __restrict__ Y) {
    int row = blockIdx.x;
    const float4* x4 = (const float4*)(X + (size_t)row * DMODEL);
    int tid = threadIdx.x;
    float4 v = x4[tid];
    float s  = v.x + v.y + v.z + v.w;
    float ss = v.x * v.x + v.y * v.y + v.z * v.z + v.w * v.w;
#pragma unroll
    for (int o = 16; o > 0; o >>= 1) {
        s  += __shfl_xor_sync(0xffffffffu, s,  o);
        ss += __shfl_xor_sync(0xffffffffu, ss, o);
    }
    __shared__ float sm_s[8], sm_ss[8];
    int wid = tid >> 5, lid = tid & 31;
    if (lid == 0) { sm_s[wid] = s; sm_ss[wid] = ss; }
    __syncthreads();
    if (tid == 0) {
        float ts = 0.f, tss = 0.f;
#pragma unroll
        for (int i = 0; i < 8; i++) { ts += sm_s[i]; tss += sm_ss[i]; }
        sm_s[0] = ts; sm_ss[0] = tss;
    }
    __syncthreads();
    float mean = sm_s[0] * (1.0f / DMODEL);
    float var  = sm_ss[0] * (1.0f / DMODEL) - mean * mean;
    float inv  = rsqrtf(var + 1e-5f);
    float4 w4 = ((const float4*)w)[tid];
    float4 b4 = ((const float4*)b)[tid];
    bf16 h[4];
    h[0] = __float2bfloat16_rn((v.x - mean) * inv * w4.x + b4.x);
    h[1] = __float2bfloat16_rn((v.y - mean) * inv * w4.y + b4.y);
    h[2] = __float2bfloat16_rn((v.z - mean) * inv * w4.z + b4.z);
    h[3] = __float2bfloat16_rn((v.w - mean) * inv * w4.w + b4.w);
    *(uint2*)(Y + (size_t)row * DMODEL + tid * 4) = *(uint2*)h;
}

// ---------------- RoPE (in place on packed QKV; Q pre-scaled) ----------------
__global__ void rope_kernel(bf16* __restrict__ QKV) {
    int idx = blockIdx.x * 256 + threadIdx.x;
    if (idx >= TOK * NH * 32) return;
    int i = idx & 31;
    int tokh = idx >> 5;
    int tok = tokh >> 4, h = tokh & 15;
    int m = tok & (MSEQ - 1);
    float invf = 1.0f / powf(10000.0f, (float)(2 * i) * (1.0f / 64.0f));
    float ang = (float)m * invf;
    float s, c;
    sincosf(ang, &s, &c);
    size_t off = (size_t)tok * QKVS + h * 64 + i;
    float q1 = __bfloat162float(QKV[off]), q2 = __bfloat162float(QKV[off + 32]);
    QKV[off]      = __float2bfloat16_rn((q1 * c - q2 * s) * SCALE_L2E);
    QKV[off + 32] = __float2bfloat16_rn((q2 * c + q1 * s) * SCALE_L2E);
    size_t ko = off + 1024;
    float k1 = __bfloat162float(QKV[ko]), k2 = __bfloat162float(QKV[ko + 32]);
    QKV[ko]      = __float2bfloat16_rn(k1 * c - k2 * s);
    QKV[ko + 32] = __float2bfloat16_rn(k2 * c + k1 * s);
}

// ---------------- Flash attention (bf16 HMMA, FA2, 3-buf KV, 1 sync/iter) ----
#define FSM_KV 18432                       // after Q (128*144)
#define KVSTG  18432                       // per stage: K 9216 + V 9216
#define FSM_BIAS (FSM_KV + 3 * KVSTG)
#define FLASHB_SMEM (FSM_BIAS + MSEQ * 4)

__global__ void __launch_bounds__(256)
flashb_kernel(const bf16* __restrict__ QKV, const int* __restrict__ mask,
              bf16* __restrict__ Og) {
    extern __shared__ char smc[];
    const uint32_t Qsu = s2u(smc);
    uint32_t Ksu[3], Vsu[3];
#pragma unroll
    for (int i = 0; i < 3; i++) {
        Ksu[i] = s2u(smc) + FSM_KV + i * KVSTG;
        Vsu[i] = s2u(smc) + FSM_KV + i * KVSTG + 9216;
    }
    float* sBias = (float*)(smc + FSM_BIAS);
    __shared__ int sAllOnes;
    const int tid = threadIdx.x, wid = tid >> 5, lane = tid & 31, g = lane >> 3;
    const int qt = blockIdx.x, h = blockIdx.y, b = blockIdx.z;
    const size_t base = ((size_t)b * MSEQ) * QKVS + h * DH;
    const bf16* Qp = QKV + base + (size_t)qt * 128 * QKVS;
    const bf16* Kp = QKV + base + 1024;
    const bf16* Vp = QKV + base + 2048;
    const int* mp = mask + b * MSEQ;

#pragma unroll
    for (int i = 0; i < 4; i++) {
        int id = tid + i * 256;
        int r = id >> 3, c = id & 7;
        cp16(Qsu + r * 144 + c * 16, Qp + (size_t)r * QKVS + c * 8);
    }
    CP_COMMIT();

    if (tid == 0) sAllOnes = 1;
    int bad = 0;
    for (int i = tid; i < MSEQ; i += 256) {
        int mv = mp[i];
        sBias[i] = mv ? 0.f : -1e30f;
        bad |= (mv == 0);
    }
    __syncthreads();
    if (bad) sAllOnes = 0;

    auto loadKV = [&](int kt, int buf) {
        const bf16* K0 = Kp + (size_t)kt * 64 * QKVS;
        const bf16* V0 = Vp + (size_t)kt * 64 * QKVS;
#pragma unroll
        for (int i = 0; i < 2; i++) {
            int id = tid + i * 256;
            int r = id >> 3, c = id & 7;
            cp16(Ksu[buf] + r * 144 + c * 16, K0 + (size_t)r * QKVS + c * 8);
            cp16(Vsu[buf] + r * 144 + c * 16, V0 + (size_t)r * QKVS + c * 8);
        }
        CP_COMMIT();
    };
    loadKV(0, 0);
    loadKV(1, 1);
    __syncthreads();                        // sAllOnes visible
    const bool allones = (sAllOnes != 0);

    uint32_t aq[4][4];
    float o[8][4];
    float m0 = -1e30f, m1 = -1e30f, l0 = 0.f, l1 = 0.f;
#pragma unroll
    for (int nj = 0; nj < 8; nj++)
#pragma unroll
        for (int q = 0; q < 4; q++) o[nj][q] = 0.f;

    const int NT = MSEQ / 64;
    int bcur = 0, bpre = 2;
    for (int kt = 0; kt < NT; kt++) {
        if (kt + 1 < NT) { CP_WAIT(1); } else { CP_WAIT(0); }
        __syncthreads();
        // 3 buffers: all warps finished reading buffer bpre in iter kt-1.
        if (kt + 2 < NT) loadKV(kt + 2, bpre);
        if (kt == 0) {
#pragma unroll
            for (int ks = 0; ks < 4; ks++) {
                int r = wid * 16 + (lane & 7) + ((g & 1) << 3);
                int cc = ks * 2 + (g >> 1);
                ldsm4(aq[ks][0], aq[ks][1], aq[ks][2], aq[ks][3],
                      Qsu + r * 144 + cc * 16);
            }
        }
        const int buf = bcur;

        float s[8][4];
#pragma unroll
        for (int ni = 0; ni < 8; ni++)
#pragma unroll
            for (int q = 0; q < 4; q++) s[ni][q] = 0.f;
#pragma unroll
        for (int ks = 0; ks < 4; ks++) {
            uint32_t bk[8][2];
#pragma unroll
            for (int np = 0; np < 4; np++) {
                int r = np * 16 + (lane & 7) + ((g >> 1) << 3);
                int cc = ks * 2 + (g & 1);
                ldsm4(bk[np * 2][0], bk[np * 2][1], bk[np * 2 + 1][0], bk[np * 2 + 1][1],
                      Ksu[buf] + r * 144 + cc * 16);
            }
#pragma unroll
            for (int ni = 0; ni < 8; ni++)
                mma16816(s[ni], aq[ks], bk[ni]);
        }

        // s already in log2e-scaled domain (Q pre-scaled in rope)
        float mx0 = -1e30f, mx1 = -1e30f;
#pragma unroll
        for (int ni = 0; ni < 8; ni++) {
            if (!allones) {
                int col = kt * 64 + ni * 8 + (lane & 3) * 2;
                float2 bb = *(float2*)&sBias[col];
                s[ni][0] += bb.x; s[ni][1] += bb.y;
                s[ni][2] += bb.x; s[ni][3] += bb.y;
            }
            mx0 = fmaxf(mx0, fmaxf(s[ni][0], s[ni][1]));
            mx1 = fmaxf(mx1, fmaxf(s[ni][2], s[ni][3]));
        }
        mx0 = fmaxf(mx0, __shfl_xor_sync(0xffffffffu, mx0, 1));
        mx0 = fmaxf(mx0, __shfl_xor_sync(0xffffffffu, mx0, 2));
        mx1 = fmaxf(mx1, __shfl_xor_sync(0xffffffffu, mx1, 1));
        mx1 = fmaxf(mx1, __shfl_xor_sync(0xffffffffu, mx1, 2));
        float mn0 = fmaxf(m0, mx0), mn1 = fmaxf(m1, mx1);
        float al0 = ex2(m0 - mn0), al1 = ex2(m1 - mn1);
        m0 = mn0; m1 = mn1;
        float sum0 = 0.f, sum1 = 0.f;
#pragma unroll
        for (int ni = 0; ni < 8; ni++) {
            s[ni][0] = ex2(s[ni][0] - mn0);
            s[ni][1] = ex2(s[ni][1] - mn0);
            s[ni][2] = ex2(s[ni][2] - mn1);
            s[ni][3] = ex2(s[ni][3] - mn1);
            sum0 += s[ni][0] + s[ni][1];
            sum1 += s[ni][2] + s[ni][3];
        }
        l0 = l0 * al0 + sum0;
        l1 = l1 * al1 + sum1;
#pragma unroll
        for (int nj = 0; nj < 8; nj++) {
            o[nj][0] *= al0; o[nj][1] *= al0;
            o[nj][2] *= al1; o[nj][3] *= al1;
        }

#pragma unroll
        for (int ks = 0; ks < 4; ks++) {
            uint32_t ap[4];
            ap[0] = packbf(s[2 * ks][0], s[2 * ks][1]);
            ap[1] = packbf(s[2 * ks][2], s[2 * ks][3]);
            ap[2] = packbf(s[2 * ks + 1][0], s[2 * ks + 1][1]);
            ap[3] = packbf(s[2 * ks + 1][2], s[2 * ks + 1][3]);
            uint32_t bv[8][2];
#pragma unroll
            for (int pr = 0; pr < 4; pr++) {
                int r = ks * 16 + (lane & 7) + ((g & 1) << 3);
                int c = pr * 16 + ((g >> 1) << 3);
                ldsm4t(bv[pr * 2][0], bv[pr * 2][1], bv[pr * 2 + 1][0], bv[pr * 2 + 1][1],
                       Vsu[buf] + r * 144 + c * 2);
            }
#pragma unroll
            for (int nj = 0; nj < 8; nj++)
                mma16816(o[nj], ap, bv[nj]);
        }
        bcur = (bcur == 2) ? 0 : bcur + 1;
        bpre = (bpre == 2) ? 0 : bpre + 1;
    }

    l0 += __shfl_xor_sync(0xffffffffu, l0, 1);
    l0 += __shfl_xor_sync(0xffffffffu, l0, 2);
    l1 += __shfl_xor_sync(0xffffffffu, l1, 1);
    l1 += __shfl_xor_sync(0xffffffffu, l1, 2);
    float inv0 = 1.0f / l0, inv1 = 1.0f / l1;

    const size_t obase = ((size_t)b * MSEQ) * DMODEL + h * DH;
    const int rlo = qt * 128 + wid * 16 + (lane >> 2);
    bf16* Ob = Og + obase;
#pragma unroll
    for (int nj = 0; nj < 8; nj++) {
        int col = nj * 8 + (lane & 3) * 2;
        *(uint32_t*)&Ob[(size_t)rlo * DMODEL + col] = packbf(o[nj][0] * inv0, o[nj][1] * inv0);
        *(uint32_t*)&Ob[(size_t)(rlo + 8) * DMODEL + col] = packbf(o[nj][2] * inv1, o[nj][3] * inv1);
    }
}

// ---------------- launch -----------------------------------------------------
extern "C" void kernel_launch(void* const* d_in, const int* in_sizes, int n_in,
                              void* d_out, int out_size) {
    const float* x    = (const float*)d_in[0];
    const int*   mask = (const int*)  d_in[1];
    const float* ln1w = (const float*)d_in[2];
    const float* ln1b = (const float*)d_in[3];
    const float* ln2w = (const float*)d_in[4];
    const float* ln2b = (const float*)d_in[5];
    const float* Uq   = (const float*)d_in[6];
    const float* Uk   = (const float*)d_in[7];
    const float* Uv   = (const float*)d_in[8];
    const float* Vq   = (const float*)d_in[9];
    const float* Vk   = (const float*)d_in[10];
    const float* Vv   = (const float*)d_in[11];
    const float* bq   = (const float*)d_in[12];
    const float* bk   = (const float*)d_in[13];
    const float* bv   = (const float*)d_in[14];
    const float* Wo   = (const float*)d_in[15];
    const float* Wob  = (const float*)d_in[16];
    const float* U1   = (const float*)d_in[17];
    const float* V1   = (const float*)d_in[18];
    const float* b1   = (const float*)d_in[19];
    const float* U2   = (const float*)d_in[20];
    const float* V2   = (const float*)d_in[21];
    const float* b2   = (const float*)d_in[22];
    float* out = (float*)d_out;

    float *x1, *bqkv;
    bf16 *xnb, *Pb, *QKVb, *AOb, *Gb, *Tb;
    bf16 *wUqkv, *wVqkv, *wWo, *wU1, *wV1, *wU2, *wV2;
    cudaGetSymbolAddress((void**)&x1,   g_x1);
    cudaGetSymbolAddress((void**)&bqkv, g_bqkv);
    cudaGetSymbolAddress((void**)&xnb,  g_xnb);
    cudaGetSymbolAddress((void**)&Pb,   g_Pb);
    cudaGetSymbolAddress((void**)&QKVb, g_QKV);
    cudaGetSymbolAddress((void**)&AOb,  g_AOb);
    cudaGetSymbolAddress((void**)&Gb,   g_Gb);
    cudaGetSymbolAddress((void**)&Tb,   g_Tb);
    cudaGetSymbolAddress((void**)&wUqkv, w_Uqkv);
    cudaGetSymbolAddress((void**)&wVqkv, w_Vqkv);
    cudaGetSymbolAddress((void**)&wWo, w_Wo);
    cudaGetSymbolAddress((void**)&wU1, w_U1);
    cudaGetSymbolAddress((void**)&wV1, w_V1);
    cudaGetSymbolAddress((void**)&wU2, w_U2);
    cudaGetSymbolAddress((void**)&wV2, w_V2);

    cudaFuncSetAttribute(flashb_kernel, cudaFuncAttributeMaxDynamicSharedMemorySize,
                         FLASHB_SMEM);
    cudaFuncSetAttribute(mma_gemm<false, false, true, false, false>,
                         cudaFuncAttributeMaxDynamicSharedMemorySize, GEMM_SMEM);
    cudaFuncSetAttribute(mma_gemm<true, false, true, false, true>,
                         cudaFuncAttributeMaxDynamicSharedMemorySize, GEMM_SMEM);
    cudaFuncSetAttribute(mma_gemm<true, true, false, false, false>,
                         cudaFuncAttributeMaxDynamicSharedMemorySize, GEMM_SMEM);
    cudaFuncSetAttribute(mma_gemm<true, false, false, true, false>,
                         cudaFuncAttributeMaxDynamicSharedMemorySize, GEMM_SMEM);

    // ---- merged weight prep (1 launch) ----
    prep_kernel<<<6657, 256>>>(Uq, Uk, Uv, Vq, Vk, Vv, Wo, U1, V1, U2, V2,
                               bq, bk, bv,
                               wUqkv, wVqkv, wWo, wU1, wV1, wU2, wV2, bqkv);

    // ---- forward ----
    ln_kernel<<<TOK, 256>>>(x, ln1w, ln1b, xnb);

    mma_gemm<false, false, true, false, false><<<dim3(6, TOK / 128), 256, GEMM_SMEM>>>(
        xnb, wUqkv, nullptr, nullptr, nullptr, Pb, 1024, 1024, 768);
    mma_gemm<true, false, true, false, true><<<dim3(24, TOK / 128), 256, GEMM_SMEM>>>(
        Pb, wVqkv, bqkv, nullptr, nullptr, QKVb, 256, 768, QKVS);

    rope_kernel<<<(TOK * NH * 32) / 256, 256>>>(QKVb);
    flashb_kernel<<<dim3(MSEQ / 128, NH, NB), 256, FLASHB_SMEM>>>(QKVb, mask, AOb);

    mma_gemm<true, true, false, false, false><<<dim3(8, TOK / 128), 256, GEMM_SMEM>>>(
        AOb, wWo, Wob, x, x1, nullptr, 1024, 1024, 1024);

    ln_kernel<<<TOK, 256>>>(x1, ln2w, ln2b, xnb);

    mma_gemm<false, false, true, false, false><<<dim3(4, TOK / 128), 256, GEMM_SMEM>>>(
        xnb, wU1, nullptr, nullptr, nullptr, Pb, 1024, 1024, 512);
    mma_gemm<true, false, false, true, false><<<dim3(32, TOK / 128), 256, GEMM_SMEM>>>(
        Pb, wV1, b1, nullptr, nullptr, Gb, 512, 512, 2048);
    mma_gemm<false, false, true, false, false><<<dim3(4, TOK / 128), 256, GEMM_SMEM>>>(
        Gb, wU2, nullptr, nullptr, nullptr, Tb, 2048, 2048, 512);
    mma_gemm<true, true, false, false, false><<<dim3(8, TOK / 128), 256, GEMM_SMEM>>>(
        Tb, wV2, b2, x1, out, nullptr, 512, 512, 1024);
}